// round 1
// baseline (speedup 1.0000x reference)
#include <cuda_runtime.h>
#include <math.h>

// Problem constants (from reference): vocab V, embed E, hidden H, batch B, steps T
#define BB 16
#define TT 128
#define HH 1024
#define EE 1024
#define VV 32000

#define K1_BLOCKS 256          // 4 hidden units per block -> 1024 units
#define K1_THREADS 256
#define K2_ROWS 16             // vocab rows per block
#define K2_BLOCKS (VV / K2_ROWS)   // 2000
#define K2_THREADS 256
#define K2_SMEM ((BB * HH + 256 + 256) * 4)   // h tile + logits + exps

// -------- persistent scratch (device globals: allocation-free) --------
__device__ float g_h[2][BB * HH];                 // ping-pong hidden state
__device__ float g_c[BB * HH];                    // cell state (in-place safe)
__device__ unsigned long long g_amax[2][BB];      // packed (orderedFloat<<32 | ~v)
__device__ float g_pexp[TT][BB][K2_BLOCKS];       // per-block exp partials (16.4 MB)

// map float -> monotonically ordered unsigned
__device__ __forceinline__ unsigned ford(float f) {
    unsigned u = __float_as_uint(f);
    return (u & 0x80000000u) ? ~u : (u | 0x80000000u);
}

// ---------------------------------------------------------------------
__global__ void k_init(const float* __restrict__ h0, const float* __restrict__ c0) {
    int i = blockIdx.x * blockDim.x + threadIdx.x;
    if (i < BB * HH) {
        g_h[0][i] = h0[i];
        g_c[i]    = c0[i];
    }
    if (i < BB) {
        // SOS token = 1: low 32 bits hold ~v
        g_amax[0][i] = (unsigned long long)(~1u);
    }
}

// ---------------------------------------------------------------------
// K1: gates = emb[tok] @ W_ih^T + b_ih + h @ W_hh^T + b_hh, then LSTM pointwise.
// Block handles 4 hidden units => 16 gate rows (i,f,g,o per unit). 8 warps, 2 rows/warp.
__global__ void __launch_bounds__(K1_THREADS)
k_lstm(int t,
       const float* __restrict__ emb,
       const float* __restrict__ Wih, const float* __restrict__ Whh,
       const float* __restrict__ bih, const float* __restrict__ bhh) {
    __shared__ float xh[16][256];      // 16 KB k-tile of concat(x, h)
    __shared__ int   tok_s[BB];
    __shared__ float gate_s[16][16];

    const int tid  = threadIdx.x;
    const int pr   = t & 1;            // read buffers
    const int cur  = (t + 1) & 1;      // write buffers

    if (tid < BB) tok_s[tid] = (int)(~(unsigned)g_amax[pr][tid]);   // decode argmax token
    if (blockIdx.x == 0 && tid < BB) g_amax[cur][tid] = 0ull;       // reset next-step argmax
    __syncthreads();

    const int warp = tid >> 5, lane = tid & 31;
    const int r0i = 2 * warp, r1i = r0i + 1;                 // local rows 0..15
    const int u0 = r0i >> 2, gs0 = r0i & 3;
    const int u1 = r1i >> 2, gs1 = r1i & 3;
    const int j0 = blockIdx.x * 4 + u0, j1 = blockIdx.x * 4 + u1;
    const int row0 = gs0 * HH + j0, row1 = gs1 * HH + j1;

    float acc0[16], acc1[16];
#pragma unroll
    for (int b = 0; b < 16; b++) { acc0[b] = 0.f; acc1[b] = 0.f; }

    for (int kt = 0; kt < 8; kt++) {
        const int kbase = kt * 256;
        // cooperative tile load: 4096 floats = 1024 float4 by 256 threads
#pragma unroll
        for (int q = 0; q < 4; q++) {
            int idx = tid + q * 256;          // float4 index
            int b   = idx >> 6;               // 64 float4 per batch row
            int kk  = (idx & 63) << 2;
            int kg  = kbase + kk;
            float4 v;
            if (kg < EE) v = *(const float4*)(emb + (size_t)tok_s[b] * EE + kg);
            else         v = *(const float4*)(g_h[pr] + b * HH + (kg - EE));
            *(float4*)(&xh[b][kk]) = v;
        }
        __syncthreads();

        const float *W0, *W1;
        if (kbase < EE) { W0 = Wih + (size_t)row0 * EE + kbase;        W1 = Wih + (size_t)row1 * EE + kbase; }
        else            { W0 = Whh + (size_t)row0 * HH + (kbase - EE); W1 = Whh + (size_t)row1 * HH + (kbase - EE); }

#pragma unroll
        for (int it = 0; it < 2; it++) {
            int k0 = lane * 4 + it * 128;
            float4 w0 = *(const float4*)(W0 + k0);
            float4 w1 = *(const float4*)(W1 + k0);
#pragma unroll
            for (int b = 0; b < 16; b++) {
                float4 hv = *(const float4*)(&xh[b][k0]);
                acc0[b] += w0.x * hv.x + w0.y * hv.y + w0.z * hv.z + w0.w * hv.w;
                acc1[b] += w1.x * hv.x + w1.y * hv.y + w1.z * hv.z + w1.w * hv.w;
            }
        }
        __syncthreads();
    }

    // warp reductions -> gate_s
#pragma unroll
    for (int b = 0; b < 16; b++) {
        float v0 = acc0[b], v1 = acc1[b];
#pragma unroll
        for (int off = 16; off; off >>= 1) {
            v0 += __shfl_xor_sync(0xFFFFFFFFu, v0, off);
            v1 += __shfl_xor_sync(0xFFFFFFFFu, v1, off);
        }
        if (lane == 0) { gate_s[r0i][b] = v0; gate_s[r1i][b] = v1; }
    }
    __syncthreads();

    // pointwise LSTM for this block's 4 units x 16 batches
    if (tid < 64) {
        int u = tid >> 4, b = tid & 15;
        int j = blockIdx.x * 4 + u;
        float gi = gate_s[u * 4 + 0][b] + bih[0 * HH + j] + bhh[0 * HH + j];
        float gf = gate_s[u * 4 + 1][b] + bih[1 * HH + j] + bhh[1 * HH + j];
        float gg = gate_s[u * 4 + 2][b] + bih[2 * HH + j] + bhh[2 * HH + j];
        float go = gate_s[u * 4 + 3][b] + bih[3 * HH + j] + bhh[3 * HH + j];
        float si = 1.f / (1.f + expf(-gi));
        float sf = 1.f / (1.f + expf(-gf));
        float so = 1.f / (1.f + expf(-go));
        float c  = sf * g_c[b * HH + j] + si * tanhf(gg);
        g_c[b * HH + j] = c;
        g_h[cur][b * HH + j] = so * tanhf(c);
    }
}

// ---------------------------------------------------------------------
// K2: logits = h @ W_lin^T + b_lin for 16 vocab rows per block.
// Writes raw logits to d_out, exp-partials to g_pexp, packed argmax via atomicMax.
__global__ void __launch_bounds__(K2_THREADS)
k_logits(int t, const float* __restrict__ Wlin, const float* __restrict__ blin,
         float* __restrict__ out) {
    extern __shared__ float sm[];
    float* h_s   = sm;                 // 16*1024
    float* log_s = sm + BB * HH;       // [16 rows][16 b]
    float* exp_s = log_s + 256;        // [16 rows][16 b]
    __shared__ unsigned long long samax[BB];

    const int tid = threadIdx.x, warp = tid >> 5, lane = tid & 31;
    const int cur = (t + 1) & 1;

    if (tid < BB) samax[tid] = 0ull;
#pragma unroll
    for (int q = 0; q < 16; q++) {
        int idx = tid + q * 256;       // float4 index over 4096
        *(float4*)(h_s + idx * 4) = *(const float4*)(g_h[cur] + idx * 4);
    }
    __syncthreads();

    const int r0 = blockIdx.x * K2_ROWS + 2 * warp, r1 = r0 + 1;
    const float* W0 = Wlin + (size_t)r0 * HH;
    const float* W1 = Wlin + (size_t)r1 * HH;

    float acc0[16], acc1[16];
#pragma unroll
    for (int b = 0; b < 16; b++) { acc0[b] = 0.f; acc1[b] = 0.f; }

#pragma unroll
    for (int it = 0; it < 8; it++) {
        int k0 = lane * 4 + it * 128;
        float4 w0 = *(const float4*)(W0 + k0);
        float4 w1 = *(const float4*)(W1 + k0);
#pragma unroll
        for (int b = 0; b < 16; b++) {
            float4 hv = *(const float4*)(h_s + b * HH + k0);
            acc0[b] += w0.x * hv.x + w0.y * hv.y + w0.z * hv.z + w0.w * hv.w;
            acc1[b] += w1.x * hv.x + w1.y * hv.y + w1.z * hv.z + w1.w * hv.w;
        }
    }

    const float bl0 = blin[r0], bl1 = blin[r1];
#pragma unroll
    for (int b = 0; b < 16; b++) {
        float v0 = acc0[b], v1 = acc1[b];
#pragma unroll
        for (int off = 16; off; off >>= 1) {
            v0 += __shfl_xor_sync(0xFFFFFFFFu, v0, off);
            v1 += __shfl_xor_sync(0xFFFFFFFFu, v1, off);
        }
        if (lane == b) {   // xor-reduce leaves result in all lanes; spread work
            float l0 = v0 + bl0, l1 = v1 + bl1;
            log_s[(2 * warp) * 16 + b]     = l0;
            log_s[(2 * warp + 1) * 16 + b] = l1;
            exp_s[(2 * warp) * 16 + b]     = expf(l0);
            exp_s[(2 * warp + 1) * 16 + b] = expf(l1);
            unsigned long long k0p = ((unsigned long long)ford(l0) << 32) | (unsigned)(~r0);
            unsigned long long k1p = ((unsigned long long)ford(l1) << 32) | (unsigned)(~r1);
            atomicMax(&samax[b], k0p > k1p ? k0p : k1p);
        }
    }
    __syncthreads();

    // write raw logits: out[b][t][v]
    {
        int b = tid >> 4, vl = tid & 15;
        out[(size_t)b * TT * VV + (size_t)t * VV + blockIdx.x * K2_ROWS + vl] = log_s[vl * 16 + b];
    }
    // exp partial (deterministic fixed-order sum) + argmax publish
    if (tid < BB) {
        float s = 0.f;
#pragma unroll
        for (int rl = 0; rl < 16; rl++) s += exp_s[rl * 16 + tid];
        g_pexp[t][tid][blockIdx.x] = s;
        atomicMax(&g_amax[cur][tid], samax[tid]);
    }
}

// ---------------------------------------------------------------------
// Final: per (t,b) reduce exp partials -> lse, subtract in place (log_softmax).
__global__ void k_final(float* __restrict__ out) {
    const int t = blockIdx.x >> 4;
    const int b = blockIdx.x & 15;
    __shared__ float red[256];
    float s = 0.f;
    for (int i = threadIdx.x; i < K2_BLOCKS; i += 256) s += g_pexp[t][b][i];
    red[threadIdx.x] = s;
    __syncthreads();
    for (int off = 128; off; off >>= 1) {
        if (threadIdx.x < off) red[threadIdx.x] += red[threadIdx.x + off];
        __syncthreads();
    }
    const float lse = logf(red[0]);
    float* p = out + (size_t)b * TT * VV + (size_t)t * VV;
    for (int i = threadIdx.x; i < VV / 4; i += 256) {
        float4 v = *(float4*)(p + i * 4);
        v.x -= lse; v.y -= lse; v.z -= lse; v.w -= lse;
        *(float4*)(p + i * 4) = v;
    }
}

__global__ void k_hc(float* __restrict__ out) {
    int i = blockIdx.x * blockDim.x + threadIdx.x;
    if (i < BB * HH) {
        out[(size_t)BB * TT * VV + i]           = g_h[0][i];  // (127+1)&1 == 0
        out[(size_t)BB * TT * VV + BB * HH + i] = g_c[i];
    }
}

// ---------------------------------------------------------------------
extern "C" void kernel_launch(void* const* d_in, const int* in_sizes, int n_in,
                              void* d_out, int out_size) {
    const float* h0   = (const float*)d_in[1];
    const float* c0   = (const float*)d_in[2];
    const float* emb  = (const float*)d_in[3];
    const float* Wih  = (const float*)d_in[4];
    const float* Whh  = (const float*)d_in[5];
    const float* bih  = (const float*)d_in[6];
    const float* bhh  = (const float*)d_in[7];
    const float* Wlin = (const float*)d_in[8];
    const float* blin = (const float*)d_in[9];
    float* out = (float*)d_out;

    cudaFuncSetAttribute(k_logits, cudaFuncAttributeMaxDynamicSharedMemorySize, K2_SMEM);

    k_init<<<(BB * HH + 255) / 256, 256>>>(h0, c0);
    for (int t = 0; t < TT; t++) {
        k_lstm<<<K1_BLOCKS, K1_THREADS>>>(t, emb, Wih, Whh, bih, bhh);
        k_logits<<<K2_BLOCKS, K2_THREADS, K2_SMEM>>>(t, Wlin, blin, out);
    }
    k_final<<<TT * BB, 256>>>(out);
    k_hc<<<(BB * HH + 255) / 256, 256>>>(out);
}

// round 3
// speedup vs baseline: 1.9568x; 1.9568x over previous
#include <cuda_runtime.h>
#include <cuda_fp16.h>
#include <math.h>
#include <stdint.h>

#define BB 16
#define TT 128
#define HH 1024
#define EE 1024
#define VV 32000

#define K1_BLOCKS 256
#define K1_THREADS 256

// ---- K2 config ----
#define K2_ROWS   128
#define K2_BLOCKS (VV / K2_ROWS)     // 250
#define K2_THREADS 256
#define NCHUNK 16                    // K chunks of 64
#define TAU 0.05f
#define WPAD 72                      // halves per W smem row (64 + 8 pad)
#define HPAD 1032                    // halves per h smem row (1024 + 8 pad)
#define LPAD 17                      // floats per log_s row

// smem offsets (bytes)
#define H_OFF    0                           // 16*1032*2      = 33024
#define W0_OFF   33024                       // 128*72*2       = 18432
#define W1_OFF   51456                       // 18432
#define LOG_OFF  69888                       // 128*17*4       = 8704
#define THR_OFF  78592                       // 16*4
#define CNT_OFF  78656                       // 16
#define CAND_OFF 78672                       // 128*4
#define K2_SMEM  79184

// -------- persistent scratch --------
__device__ float  g_h[2][BB * HH];
__device__ float  g_c[BB * HH];
__device__ __half g_h16[BB * HH];
__device__ __half g_W16[(size_t)VV * HH];        // 64 MB fp16 W_lin
__device__ unsigned long long g_amax[2][BB];     // exact packed argmax
__device__ unsigned g_approx[2][BB];             // approx running max (ford)
__device__ float  g_pexp[TT][BB][K2_BLOCKS];

// ---------------- helpers ----------------
__device__ __forceinline__ unsigned ford(float f) {
    unsigned u = __float_as_uint(f);
    return (u & 0x80000000u) ? ~u : (u | 0x80000000u);
}
__device__ __forceinline__ float funord(unsigned v) {
    unsigned bits = (v & 0x80000000u) ? (v ^ 0x80000000u) : ~v;
    return __uint_as_float(bits);
}
#define CP16(dst, src)  asm volatile("cp.async.cg.shared.global [%0], [%1], 16;" :: "r"(dst), "l"(src) : "memory")
#define CP_COMMIT()     asm volatile("cp.async.commit_group;" ::: "memory")
#define CP_WAIT1()      asm volatile("cp.async.wait_group 1;" ::: "memory")
#define CP_WAIT0()      asm volatile("cp.async.wait_group 0;" ::: "memory")

__device__ __forceinline__ uint32_t smem_u32(const void* p) {
    uint32_t a;
    asm("{ .reg .u64 t; cvta.to.shared.u64 t, %1; cvt.u32.u64 %0, t; }" : "=r"(a) : "l"(p));
    return a;
}
__device__ __forceinline__ void mma16816(float* c, uint32_t a0, uint32_t a1,
                                         uint32_t a2, uint32_t a3,
                                         uint32_t b0, uint32_t b1) {
    asm volatile(
        "mma.sync.aligned.m16n8k16.row.col.f32.f16.f16.f32 "
        "{%0,%1,%2,%3}, {%4,%5,%6,%7}, {%8,%9}, {%0,%1,%2,%3};"
        : "+f"(c[0]), "+f"(c[1]), "+f"(c[2]), "+f"(c[3])
        : "r"(a0), "r"(a1), "r"(a2), "r"(a3), "r"(b0), "r"(b1));
}

// ---------------------------------------------------------------------
__global__ void k_init(const float* __restrict__ h0, const float* __restrict__ c0) {
    int i = blockIdx.x * blockDim.x + threadIdx.x;
    if (i < BB * HH) {
        g_h[0][i] = h0[i];
        g_c[i]    = c0[i];
    }
    if (i < BB) g_amax[0][i] = (unsigned long long)(~1u);   // SOS token = 1
}

__global__ void k_cvt(const float* __restrict__ W) {
    size_t i = ((size_t)blockIdx.x * 256 + threadIdx.x) * 8;
    float4 a = *(const float4*)(W + i);
    float4 b = *(const float4*)(W + i + 4);
    __half2 p0 = __floats2half2_rn(a.x, a.y), p1 = __floats2half2_rn(a.z, a.w);
    __half2 p2 = __floats2half2_rn(b.x, b.y), p3 = __floats2half2_rn(b.z, b.w);
    uint4 o;
    o.x = *(uint32_t*)&p0; o.y = *(uint32_t*)&p1;
    o.z = *(uint32_t*)&p2; o.w = *(uint32_t*)&p3;
    *(uint4*)(g_W16 + i) = o;
}

// ---------------------------------------------------------------------
// K1: fp32 LSTM step; also emits fp16 h for K2.
__global__ void __launch_bounds__(K1_THREADS)
k_lstm(int t,
       const float* __restrict__ emb,
       const float* __restrict__ Wih, const float* __restrict__ Whh,
       const float* __restrict__ bih, const float* __restrict__ bhh) {
    __shared__ float xh[16][256];
    __shared__ int   tok_s[BB];
    __shared__ float gate_s[16][16];

    const int tid  = threadIdx.x;
    const int pr   = t & 1;
    const int cur  = (t + 1) & 1;

    if (tid < BB) tok_s[tid] = (int)(~(unsigned)g_amax[pr][tid]);
    if (blockIdx.x == 0 && tid < BB) { g_amax[cur][tid] = 0ull; g_approx[cur][tid] = 0u; }
    __syncthreads();

    const int warp = tid >> 5, lane = tid & 31;
    const int r0i = 2 * warp, r1i = r0i + 1;
    const int u0 = r0i >> 2, gs0 = r0i & 3;
    const int u1 = r1i >> 2, gs1 = r1i & 3;
    const int j0 = blockIdx.x * 4 + u0, j1 = blockIdx.x * 4 + u1;
    const int row0 = gs0 * HH + j0, row1 = gs1 * HH + j1;

    float acc0[16], acc1[16];
#pragma unroll
    for (int b = 0; b < 16; b++) { acc0[b] = 0.f; acc1[b] = 0.f; }

    for (int kt = 0; kt < 8; kt++) {
        const int kbase = kt * 256;
#pragma unroll
        for (int q = 0; q < 4; q++) {
            int idx = tid + q * 256;
            int b   = idx >> 6;
            int kk  = (idx & 63) << 2;
            int kg  = kbase + kk;
            float4 v;
            if (kg < EE) v = *(const float4*)(emb + (size_t)tok_s[b] * EE + kg);
            else         v = *(const float4*)(g_h[pr] + b * HH + (kg - EE));
            *(float4*)(&xh[b][kk]) = v;
        }
        __syncthreads();

        const float *W0, *W1;
        if (kbase < EE) { W0 = Wih + (size_t)row0 * EE + kbase;        W1 = Wih + (size_t)row1 * EE + kbase; }
        else            { W0 = Whh + (size_t)row0 * HH + (kbase - EE); W1 = Whh + (size_t)row1 * HH + (kbase - EE); }

#pragma unroll
        for (int it = 0; it < 2; it++) {
            int k0 = lane * 4 + it * 128;
            float4 w0 = *(const float4*)(W0 + k0);
            float4 w1 = *(const float4*)(W1 + k0);
#pragma unroll
            for (int b = 0; b < 16; b++) {
                float4 hv = *(const float4*)(&xh[b][k0]);
                acc0[b] += w0.x * hv.x + w0.y * hv.y + w0.z * hv.z + w0.w * hv.w;
                acc1[b] += w1.x * hv.x + w1.y * hv.y + w1.z * hv.z + w1.w * hv.w;
            }
        }
        __syncthreads();
    }

#pragma unroll
    for (int b = 0; b < 16; b++) {
        float v0 = acc0[b], v1 = acc1[b];
#pragma unroll
        for (int off = 16; off; off >>= 1) {
            v0 += __shfl_xor_sync(0xFFFFFFFFu, v0, off);
            v1 += __shfl_xor_sync(0xFFFFFFFFu, v1, off);
        }
        if (lane == 0) { gate_s[r0i][b] = v0; gate_s[r1i][b] = v1; }
    }
    __syncthreads();

    if (tid < 64) {
        int u = tid >> 4, b = tid & 15;
        int j = blockIdx.x * 4 + u;
        float gi = gate_s[u * 4 + 0][b] + bih[0 * HH + j] + bhh[0 * HH + j];
        float gf = gate_s[u * 4 + 1][b] + bih[1 * HH + j] + bhh[1 * HH + j];
        float gg = gate_s[u * 4 + 2][b] + bih[2 * HH + j] + bhh[2 * HH + j];
        float go = gate_s[u * 4 + 3][b] + bih[3 * HH + j] + bhh[3 * HH + j];
        float si = 1.f / (1.f + expf(-gi));
        float sf = 1.f / (1.f + expf(-gf));
        float so = 1.f / (1.f + expf(-go));
        float c  = sf * g_c[b * HH + j] + si * tanhf(gg);
        g_c[b * HH + j] = c;
        float h = so * tanhf(c);
        g_h[cur][b * HH + j] = h;
        g_h16[b * HH + j] = __float2half(h);
    }
}

// ---------------------------------------------------------------------
// K2: fp16 HMMA GEMM (128 vocab rows x 16 batch x K=1024) + epilogue + exact rescue
__global__ void __launch_bounds__(K2_THREADS)
k_logits(int t, const float* __restrict__ Wlin, const float* __restrict__ blin,
         float* __restrict__ out) {
    extern __shared__ char sm[];
    const uint32_t smem_base = smem_u32(sm);
    __half* h_s   = (__half*)(sm + H_OFF);
    float*  log_s = (float*)(sm + LOG_OFF);
    float*  thr_s = (float*)(sm + THR_OFF);
    int*    cnt_s = (int*)(sm + CNT_OFF);
    int*    cand_s = (int*)(sm + CAND_OFF);

    const int tid = threadIdx.x, warp = tid >> 5, lane = tid & 31;
    const int cur = (t + 1) & 1;
    const int r = lane >> 2, q4 = lane & 3;

    if (tid == 0) *cnt_s = 0;

    // load h16 into padded smem [16][HPAD]
#pragma unroll
    for (int q = 0; q < 8; q++) {
        int i = tid + q * 256;          // 16B unit index (128 per batch row)
        int b = i >> 7, k8 = i & 127;
        float4 v = *(const float4*)(g_h16 + (size_t)b * HH + k8 * 8);
        *(float4*)(h_s + b * HPAD + k8 * 8) = v;
    }

    const size_t wrow_base = (size_t)blockIdx.x * K2_ROWS * HH;
    // prefetch chunk 0
#pragma unroll
    for (int qq = 0; qq < 4; qq++) {
        int i = tid + qq * 256;
        int row = i >> 3, col16 = i & 7;
        CP16(smem_base + W0_OFF + (uint32_t)(row * WPAD + col16 * 8) * 2,
             g_W16 + wrow_base + (size_t)row * HH + col16 * 8);
    }
    CP_COMMIT();

    float acc0[4] = {0.f, 0.f, 0.f, 0.f};
    float acc1[4] = {0.f, 0.f, 0.f, 0.f};

    for (int c = 0; c < NCHUNK; c++) {
        if (c + 1 < NCHUNK) {
            uint32_t wb_off = ((c + 1) & 1) ? W1_OFF : W0_OFF;
#pragma unroll
            for (int qq = 0; qq < 4; qq++) {
                int i = tid + qq * 256;
                int row = i >> 3, col16 = i & 7;
                CP16(smem_base + wb_off + (uint32_t)(row * WPAD + col16 * 8) * 2,
                     g_W16 + wrow_base + (size_t)row * HH + (c + 1) * 64 + col16 * 8);
            }
            CP_COMMIT();
            CP_WAIT1();
        } else {
            CP_WAIT0();
        }
        __syncthreads();

        const __half* wb = (const __half*)(sm + ((c & 1) ? W1_OFF : W0_OFF));
        const int kbase = c * 64;
#pragma unroll
        for (int ks = 0; ks < 4; ks++) {
            int k0 = ks * 16 + q4 * 2;
            uint32_t a0 = *(const uint32_t*)(wb + (warp * 16 + r) * WPAD + k0);
            uint32_t a1 = *(const uint32_t*)(wb + (warp * 16 + r + 8) * WPAD + k0);
            uint32_t a2 = *(const uint32_t*)(wb + (warp * 16 + r) * WPAD + k0 + 8);
            uint32_t a3 = *(const uint32_t*)(wb + (warp * 16 + r + 8) * WPAD + k0 + 8);
            int kg = kbase + k0;
            uint32_t b00 = *(const uint32_t*)(h_s + r * HPAD + kg);
            uint32_t b01 = *(const uint32_t*)(h_s + r * HPAD + kg + 8);
            uint32_t b10 = *(const uint32_t*)(h_s + (r + 8) * HPAD + kg);
            uint32_t b11 = *(const uint32_t*)(h_s + (r + 8) * HPAD + kg + 8);
            mma16816(acc0, a0, a1, a2, a3, b00, b01);
            mma16816(acc1, a0, a1, a2, a3, b10, b11);
        }
        __syncthreads();
    }

    // ---- epilogue: bias + stage to log_s ----
    {
        const int rbase = warp * 16 + r;
        const float bl0 = blin[blockIdx.x * K2_ROWS + rbase];
        const float bl1 = blin[blockIdx.x * K2_ROWS + rbase + 8];
        const int c0 = q4 * 2;
        log_s[rbase * LPAD + c0]           = acc0[0] + bl0;
        log_s[rbase * LPAD + c0 + 1]       = acc0[1] + bl0;
        log_s[(rbase + 8) * LPAD + c0]     = acc0[2] + bl1;
        log_s[(rbase + 8) * LPAD + c0 + 1] = acc0[3] + bl1;
        log_s[rbase * LPAD + c0 + 8]       = acc1[0] + bl0;
        log_s[rbase * LPAD + c0 + 9]       = acc1[1] + bl0;
        log_s[(rbase + 8) * LPAD + c0 + 8] = acc1[2] + bl1;
        log_s[(rbase + 8) * LPAD + c0 + 9] = acc1[3] + bl1;
    }
    __syncthreads();

    // write raw logits (coalesced per batch)
#pragma unroll
    for (int i = 0; i < 8; i++) {
        int idx = tid + i * 256;
        int row = idx & 127, b = idx >> 7;
        out[(size_t)b * TT * VV + (size_t)t * VV + blockIdx.x * K2_ROWS + row] =
            log_s[row * LPAD + b];
    }

    // per-batch exp-sum + approx max: warp w handles batches 2w, 2w+1
    {
        int b = 2 * warp + (lane >> 4);
        int l = lane & 15;
        float s = 0.f, m = -1e30f;
#pragma unroll
        for (int rr = 0; rr < 8; rr++) {
            float v = log_s[(l * 8 + rr) * LPAD + b];
            s += expf(v);
            m = fmaxf(m, v);
        }
#pragma unroll
        for (int off = 8; off; off >>= 1) {
            s += __shfl_xor_sync(0xFFFFFFFFu, s, off);
            m = fmaxf(m, __shfl_xor_sync(0xFFFFFFFFu, m, off));
        }
        if (l == 0) {
            g_pexp[t][b][blockIdx.x] = s;
            unsigned fm = ford(m);
            unsigned old = atomicMax(&g_approx[cur][b], fm);
            unsigned L = old > fm ? old : fm;
            thr_s[b] = funord(L) - TAU;
        }
    }
    __syncthreads();

    // candidate scan
#pragma unroll
    for (int i = 0; i < 8; i++) {
        int idx = tid + i * 256;
        int row = idx & 127, b = idx >> 7;
        if (log_s[row * LPAD + b] >= thr_s[b]) {
            int slot = atomicAdd(cnt_s, 1);
            if (slot < 128) cand_s[slot] = ((blockIdx.x * K2_ROWS + row) << 4) | b;
        }
    }
    __syncthreads();

    // exact fp32 rescue: one warp per candidate
    int n = *cnt_s; if (n > 128) n = 128;
    for (int e = warp; e < n; e += 8) {
        int pk = cand_s[e];
        int rr = pk >> 4, b = pk & 15;
        const float4* Wr = (const float4*)(Wlin + (size_t)rr * HH);
        const float4* hr = (const float4*)(g_h[cur] + b * HH);
        float acc = 0.f;
#pragma unroll
        for (int qq = 0; qq < 8; qq++) {
            float4 w = Wr[lane + qq * 32];
            float4 h = hr[lane + qq * 32];
            acc += w.x * h.x + w.y * h.y + w.z * h.z + w.w * h.w;
        }
#pragma unroll
        for (int off = 16; off; off >>= 1) acc += __shfl_xor_sync(0xFFFFFFFFu, acc, off);
        if (lane == 0) {
            float ex = acc + blin[rr];
            unsigned long long pkd =
                ((unsigned long long)ford(ex) << 32) | (unsigned)(~(unsigned)rr);
            atomicMax(&g_amax[cur][b], pkd);
        }
    }
}

// ---------------------------------------------------------------------
__global__ void k_final(float* __restrict__ out) {
    const int t = blockIdx.x >> 4;
    const int b = blockIdx.x & 15;
    __shared__ float red[256];
    float s = 0.f;
    for (int i = threadIdx.x; i < K2_BLOCKS; i += 256) s += g_pexp[t][b][i];
    red[threadIdx.x] = s;
    __syncthreads();
    for (int off = 128; off; off >>= 1) {
        if (threadIdx.x < off) red[threadIdx.x] += red[threadIdx.x + off];
        __syncthreads();
    }
    const float lse = logf(red[0]);
    float* p = out + (size_t)b * TT * VV + (size_t)t * VV;
    for (int i = threadIdx.x; i < VV / 4; i += 256) {
        float4 v = *(float4*)(p + i * 4);
        v.x -= lse; v.y -= lse; v.z -= lse; v.w -= lse;
        *(float4*)(p + i * 4) = v;
    }
}

__global__ void k_hc(float* __restrict__ out) {
    int i = blockIdx.x * blockDim.x + threadIdx.x;
    if (i < BB * HH) {
        out[(size_t)BB * TT * VV + i]           = g_h[0][i];
        out[(size_t)BB * TT * VV + BB * HH + i] = g_c[i];
    }
}

// ---------------------------------------------------------------------
extern "C" void kernel_launch(void* const* d_in, const int* in_sizes, int n_in,
                              void* d_out, int out_size) {
    const float* h0   = (const float*)d_in[1];
    const float* c0   = (const float*)d_in[2];
    const float* emb  = (const float*)d_in[3];
    const float* Wih  = (const float*)d_in[4];
    const float* Whh  = (const float*)d_in[5];
    const float* bih  = (const float*)d_in[6];
    const float* bhh  = (const float*)d_in[7];
    const float* Wlin = (const float*)d_in[8];
    const float* blin = (const float*)d_in[9];
    float* out = (float*)d_out;

    cudaFuncSetAttribute(k_logits, cudaFuncAttributeMaxDynamicSharedMemorySize, K2_SMEM);

    k_init<<<(BB * HH + 255) / 256, 256>>>(h0, c0);
    k_cvt<<<(int)((size_t)VV * HH / 8 / 256), 256>>>(Wlin);
    for (int t = 0; t < TT; t++) {
        k_lstm<<<K1_BLOCKS, K1_THREADS>>>(t, emb, Wih, Whh, bih, bhh);
        k_logits<<<K2_BLOCKS, K2_THREADS, K2_SMEM>>>(t, Wlin, blin, out);
    }
    k_final<<<TT * BB, 256>>>(out);
    k_hc<<<(BB * HH + 255) / 256, 256>>>(out);
}